// round 4
// baseline (speedup 1.0000x reference)
#include <cuda_runtime.h>
#include <cstdint>
#include <cstddef>

// EdgeEncoder fused: out = relu(relu([U|V|sel] @ W1 + b1) @ W2 + b2)
// Decomposed as U@W1a + V@W1b + sel*w1c (rank-1) to keep gathers as clean
// 128-wide K GEMMs. tf32 mma.sync with fp32 accumulation.
// NOTE: edge_index is int32 (JAX default config downcasts jnp.int64 -> int32).

#define LDX 132   // Xs row stride (floats): (row*4+k)%32 distinct -> conflict-free A frags
#define LDW 136   // Ws row stride (floats): (k*8+n)%32 distinct  -> conflict-free B frags
#define MTILE 128

__device__ __forceinline__ float f2tf(float f) {
    uint32_t r;
    asm("cvt.rna.tf32.f32 %0, %1;" : "=r"(r) : "f"(f));
    return __uint_as_float(r);
}

__device__ __forceinline__ void mma8(float c[4], const uint32_t a[4], uint32_t b0, uint32_t b1) {
    asm("mma.sync.aligned.m16n8k8.row.col.f32.tf32.tf32.f32 "
        "{%0,%1,%2,%3}, {%4,%5,%6,%7}, {%8,%9}, {%0,%1,%2,%3};"
        : "+f"(c[0]), "+f"(c[1]), "+f"(c[2]), "+f"(c[3])
        : "r"(a[0]), "r"(a[1]), "r"(a[2]), "r"(a[3]), "r"(b0), "r"(b1));
}

// One 128x128x128 GEMM pass: Xs (A, tf32 bits) x Ws (B, tf32 bits) -> acc (fp32)
__device__ __forceinline__ void gemm_pass(const float* __restrict__ Xs,
                                          const float* __restrict__ Ws,
                                          float acc[2][8][4],
                                          int m_warp, int n_warp, int gq, int tq) {
#pragma unroll
    for (int ks = 0; ks < 16; ++ks) {
        const int k0 = ks * 8;
        uint32_t a[2][4];
#pragma unroll
        for (int mt = 0; mt < 2; ++mt) {
            const int r0 = m_warp + mt * 16 + gq;
            a[mt][0] = __float_as_uint(Xs[r0 * LDX + k0 + tq]);
            a[mt][1] = __float_as_uint(Xs[(r0 + 8) * LDX + k0 + tq]);
            a[mt][2] = __float_as_uint(Xs[r0 * LDX + k0 + tq + 4]);
            a[mt][3] = __float_as_uint(Xs[(r0 + 8) * LDX + k0 + tq + 4]);
        }
#pragma unroll
        for (int nt = 0; nt < 8; ++nt) {
            const int n0 = n_warp + nt * 8 + gq;
            const uint32_t bb0 = __float_as_uint(Ws[(k0 + tq) * LDW + n0]);
            const uint32_t bb1 = __float_as_uint(Ws[(k0 + tq + 4) * LDW + n0]);
            mma8(acc[0][nt], a[0], bb0, bb1);
            mma8(acc[1][nt], a[1], bb0, bb1);
        }
    }
}

__device__ __forceinline__ void load_w_tile(float* __restrict__ Ws,
                                            const float* __restrict__ src_f,
                                            int tid) {
    const float4* src = reinterpret_cast<const float4*>(src_f);
#pragma unroll
    for (int i = tid; i < 128 * 32; i += 256) {
        const int k = i >> 5, c = i & 31;
        float4 v = src[i];
        float4 w;
        w.x = f2tf(v.x); w.y = f2tf(v.y); w.z = f2tf(v.z); w.w = f2tf(v.w);
        reinterpret_cast<float4*>(Ws + k * LDW + c * 4)[0] = w;
    }
}

__global__ void __launch_bounds__(256) edge_mlp_kernel(
    const float* __restrict__ node_emb,
    const int* __restrict__ edge_index,     // int32!
    const float* __restrict__ edge_sel,
    const float* __restrict__ W1,
    const float* __restrict__ b1,
    const float* __restrict__ W2,
    const float* __restrict__ b2,
    float* __restrict__ out,
    int E, int blocks_per_batch, int n_nodes)
{
    extern __shared__ float smem[];
    float* Xs   = smem;                  // 128*LDX
    float* Ws   = Xs + MTILE * LDX;      // 128*LDW
    float* selv = Ws + 128 * LDW;        // 128
    float* b1s  = selv + 128;            // 128
    float* w1cs = b1s + 128;             // 128
    float* b2s  = w1cs + 128;            // 128

    const int tid  = threadIdx.x;
    const int wid  = tid >> 5;
    const int lane = tid & 31;
    const int gq   = lane >> 2;   // group-of-4 id (0..7)
    const int tq   = lane & 3;    // thread-in-group (0..3)
    const int m_warp = (wid & 3) * 32;
    const int n_warp = (wid >> 2) * 64;

    const int b_idx = blockIdx.x / blocks_per_batch;
    const int tile  = blockIdx.x - b_idx * blocks_per_batch;
    const long long edge_base = (long long)b_idx * E + (long long)tile * MTILE;
    const float* node_base = node_emb + (size_t)b_idx * (size_t)n_nodes * 128;

    if (tid < 128) {
        b1s[tid]  = b1[tid];
        w1cs[tid] = W1[256 * 128 + tid];
        b2s[tid]  = b2[tid];
        selv[tid] = edge_sel[edge_base + tid];
    }

    float acc[2][8][4];
#pragma unroll
    for (int mt = 0; mt < 2; ++mt)
#pragma unroll
        for (int nt = 0; nt < 8; ++nt)
#pragma unroll
            for (int i = 0; i < 4; ++i) acc[mt][nt][i] = 0.f;

    // ---- Phase 1 & 2: accumulate U@W1a + V@W1b ----
    for (int side = 0; side < 2; ++side) {
        // Gather node rows into Xs (2 threads per row, float4, tf32-round)
        {
            const int r = tid >> 1;
            const int h = tid & 1;
            int idx = edge_index[(edge_base + r) * 2 + side];
            if (idx < 0) idx = 0;
            if (idx >= n_nodes) idx = n_nodes - 1;
            const float4* src = reinterpret_cast<const float4*>(node_base + (size_t)idx * 128) + h * 16;
            float4* dst = reinterpret_cast<float4*>(Xs + r * LDX + h * 64);
#pragma unroll
            for (int i = 0; i < 16; ++i) {
                float4 v = src[i];
                float4 w;
                w.x = f2tf(v.x); w.y = f2tf(v.y); w.z = f2tf(v.z); w.w = f2tf(v.w);
                dst[i] = w;
            }
        }
        load_w_tile(Ws, W1 + side * 128 * 128, tid);
        __syncthreads();
        gemm_pass(Xs, Ws, acc, m_warp, n_warp, gq, tq);
        __syncthreads();   // all reads done before next overwrite of Xs/Ws
    }

    // ---- Epilogue 1: h = relu(acc + b1 + sel*w1c); write H (tf32) to Xs ----
#pragma unroll
    for (int nt = 0; nt < 8; ++nt) {
        const int n0 = n_warp + nt * 8 + tq * 2;
        const float wc0 = w1cs[n0], wc1 = w1cs[n0 + 1];
        const float bv0 = b1s[n0],  bv1 = b1s[n0 + 1];
#pragma unroll
        for (int mt = 0; mt < 2; ++mt) {
            const int r0 = m_warp + mt * 16 + gq;
            const float s0 = selv[r0], s1 = selv[r0 + 8];
            Xs[r0 * LDX + n0]           = f2tf(fmaxf(acc[mt][nt][0] + bv0 + s0 * wc0, 0.f));
            Xs[r0 * LDX + n0 + 1]       = f2tf(fmaxf(acc[mt][nt][1] + bv1 + s0 * wc1, 0.f));
            Xs[(r0 + 8) * LDX + n0]     = f2tf(fmaxf(acc[mt][nt][2] + bv0 + s1 * wc0, 0.f));
            Xs[(r0 + 8) * LDX + n0 + 1] = f2tf(fmaxf(acc[mt][nt][3] + bv1 + s1 * wc1, 0.f));
            acc[mt][nt][0] = acc[mt][nt][1] = acc[mt][nt][2] = acc[mt][nt][3] = 0.f;
        }
    }
    load_w_tile(Ws, W2, tid);
    __syncthreads();

    // ---- GEMM 2: H @ W2 ----
    gemm_pass(Xs, Ws, acc, m_warp, n_warp, gq, tq);

    // ---- Epilogue 2: relu(acc + b2) -> out ----
#pragma unroll
    for (int nt = 0; nt < 8; ++nt) {
        const int n0 = n_warp + nt * 8 + tq * 2;
        const float bv0 = b2s[n0], bv1 = b2s[n0 + 1];
#pragma unroll
        for (int mt = 0; mt < 2; ++mt) {
            const int r0 = m_warp + mt * 16 + gq;
            float2 o0 = make_float2(fmaxf(acc[mt][nt][0] + bv0, 0.f),
                                    fmaxf(acc[mt][nt][1] + bv1, 0.f));
            float2 o1 = make_float2(fmaxf(acc[mt][nt][2] + bv0, 0.f),
                                    fmaxf(acc[mt][nt][3] + bv1, 0.f));
            *reinterpret_cast<float2*>(out + (size_t)(edge_base + r0) * 128 + n0)     = o0;
            *reinterpret_cast<float2*>(out + (size_t)(edge_base + r0 + 8) * 128 + n0) = o1;
        }
    }
}

extern "C" void kernel_launch(void* const* d_in, const int* in_sizes, int n_in,
                              void* d_out, int out_size) {
    const float* node_emb   = (const float*)d_in[0];
    const int*   edge_index = (const int*)d_in[1];     // int32 (JAX x64 disabled)
    const float* edge_sel   = (const float*)d_in[2];
    const float* W1         = (const float*)d_in[3];
    const float* b1         = (const float*)d_in[4];
    const float* W2         = (const float*)d_in[5];
    const float* b2         = (const float*)d_in[6];
    float*       out        = (float*)d_out;

    const int B  = 4;
    const int BE = in_sizes[2];             // B * E * EXTRA(=1)
    const int E  = BE / B;
    const int n_nodes = in_sizes[0] / (B * 128);
    const int blocks_per_batch = E / MTILE;
    const int grid = B * blocks_per_batch;

    const size_t smem_bytes = (size_t)(MTILE * LDX + 128 * LDW + 4 * 128) * sizeof(float);
    cudaFuncSetAttribute(edge_mlp_kernel,
                         cudaFuncAttributeMaxDynamicSharedMemorySize, (int)smem_bytes);

    edge_mlp_kernel<<<grid, 256, smem_bytes>>>(
        node_emb, edge_index, edge_sel, W1, b1, W2, b2, out,
        E, blocks_per_batch, n_nodes);
}